// round 1
// baseline (speedup 1.0000x reference)
#include <cuda_runtime.h>

// ---------------------------------------------------------------------------
// GA (3,0,0) fused dense layer:
//   out[k*B+b, d] = sum_j s(k,j) * ( x[i(k,j)*B+b, :] @ W[:, j*D+d] ) + bias[k*D+d]
// Single GEMM M=16384, N=2048, K=16384 with per-K-block (j) operand gather.
// ---------------------------------------------------------------------------

#define BM 128
#define BN 128
#define BK 16
#define TM 8
#define TN 8
#define NTHREADS 256
#define BMP 132   // padded As row length (float4-aligned, reduces STS conflicts)

// Cayley table for blades ['','1','2','3','12','13','23','123'], e_i^2=+1.
// c_kij[i*8+j] = k such that blade_i * blade_j = s * blade_k
__device__ __constant__ int c_kij[64] = {
    0,1,2,3,4,5,6,7,
    1,0,4,5,2,3,7,6,
    2,4,0,6,1,7,3,5,
    3,5,6,0,7,1,2,4,
    4,2,1,7,0,6,5,3,
    5,3,7,1,6,0,4,2,
    6,7,3,2,5,4,0,1,
    7,6,5,4,3,2,1,0};
__device__ __constant__ float c_sij[64] = {
    1.f, 1.f, 1.f, 1.f, 1.f, 1.f, 1.f, 1.f,
    1.f, 1.f, 1.f, 1.f, 1.f, 1.f, 1.f, 1.f,
    1.f,-1.f, 1.f, 1.f,-1.f,-1.f, 1.f,-1.f,
    1.f,-1.f,-1.f, 1.f, 1.f,-1.f,-1.f, 1.f,
    1.f,-1.f, 1.f, 1.f,-1.f,-1.f, 1.f,-1.f,
    1.f,-1.f,-1.f, 1.f, 1.f,-1.f,-1.f, 1.f,
    1.f, 1.f,-1.f, 1.f,-1.f, 1.f,-1.f,-1.f,
    1.f, 1.f,-1.f, 1.f,-1.f, 1.f,-1.f,-1.f};

// For output blade-block kblk and K-block j, find the unique input blade i and
// sign s with C[kblk, i, j] = s  (i.e. c_kij[i*8+j] == kblk).
__device__ __forceinline__ void gather_info(int kblk, int j, int& ib, float& sg)
{
    int   ibv = 0;
    float sv  = 1.f;
#pragma unroll
    for (int ii = 0; ii < 8; ++ii) {
        bool m = (c_kij[ii * 8 + j] == kblk);
        ibv = m ? ii : ibv;
        sv  = m ? c_sij[ii * 8 + j] : sv;
    }
    ib = ibv;
    sg = sv;
}

__global__ __launch_bounds__(NTHREADS, 2)
void ga_dense_gemm(const float* __restrict__ X,     // [8*B, DIN]
                   const float* __restrict__ W,     // [DIN, 8*D]
                   const float* __restrict__ bias,  // [8*D]
                   float* __restrict__ out)         // [8*B, D]
{
    constexpr int B   = 2048;
    constexpr int DIN = 2048;
    constexpr int U   = 16384;   // 8*D
    constexpr int D   = 2048;
    constexpr int NKT = (8 * DIN) / BK;      // 1024 K-tiles total
    constexpr int KT_PER_J = DIN / BK;       // 128 K-tiles per j-block

    const int bn   = blockIdx.x;             // 0..15   (N tiles)
    const int bm   = blockIdx.y;             // 0..127  (M tiles)
    const int kblk = (bm * BM) / B;          // output blade index (tile never crosses)
    const int rloc = (bm * BM) % B;          // within-blade row base

    __shared__ float As[2][BK][BMP];
    __shared__ float Bs[2][BK][BN];

    const int t     = threadIdx.x;
    const int a_row = t >> 2;                // 0..63
    const int a_col = (t & 3) << 2;          // 0,4,8,12 (K offset inside tile)
    const int b_row = t >> 5;                // 0..7
    const int b_col = (t & 31) << 2;         // 0..124
    const int tx    = t & 15;
    const int ty    = t >> 4;

    float acc[TM][TN];
#pragma unroll
    for (int m = 0; m < TM; ++m)
#pragma unroll
        for (int n = 0; n < TN; ++n) acc[m][n] = 0.f;

    // staging registers for the software pipeline
    float4 ra0, ra1, rb0, rb1;
    float  rsg = 1.f;

    // ---- load tile kt into staging registers ----
    auto load_tile = [&](int kt) {
        const int j  = kt / KT_PER_J;                 // 0..7
        const int c0 = (kt % KT_PER_J) * BK;          // local K offset in [0,2048)
        int ib; float sg;
        gather_info(kblk, j, ib, sg);
        rsg = sg;
        const float* Ap = X + (size_t)(ib * B + rloc) * DIN + c0;
        ra0 = *reinterpret_cast<const float4*>(Ap + (size_t)a_row * DIN + a_col);
        ra1 = *reinterpret_cast<const float4*>(Ap + (size_t)(a_row + 64) * DIN + a_col);
        const float* Bp = W + (size_t)c0 * U + j * D + bn * BN;
        rb0 = *reinterpret_cast<const float4*>(Bp + (size_t)b_row * U + b_col);
        rb1 = *reinterpret_cast<const float4*>(Bp + (size_t)(b_row + 8) * U + b_col);
    };

    // ---- store staging registers into smem buffer `buf` ----
    auto store_tile = [&](int buf) {
        // A stored transposed (K-major) with sign folded in
        As[buf][a_col + 0][a_row] = ra0.x * rsg;
        As[buf][a_col + 1][a_row] = ra0.y * rsg;
        As[buf][a_col + 2][a_row] = ra0.z * rsg;
        As[buf][a_col + 3][a_row] = ra0.w * rsg;
        As[buf][a_col + 0][a_row + 64] = ra1.x * rsg;
        As[buf][a_col + 1][a_row + 64] = ra1.y * rsg;
        As[buf][a_col + 2][a_row + 64] = ra1.z * rsg;
        As[buf][a_col + 3][a_row + 64] = ra1.w * rsg;
        *reinterpret_cast<float4*>(&Bs[buf][b_row][b_col])     = rb0;
        *reinterpret_cast<float4*>(&Bs[buf][b_row + 8][b_col]) = rb1;
    };

    // prologue
    load_tile(0);
    store_tile(0);
    __syncthreads();

    for (int kt = 0; kt < NKT; ++kt) {
        const int buf = kt & 1;
        if (kt + 1 < NKT) load_tile(kt + 1);

        // ---- compute on buffer `buf` ----
#pragma unroll
        for (int kk = 0; kk < BK; ++kk) {
            float4 av0 = *reinterpret_cast<const float4*>(&As[buf][kk][ty * TM]);
            float4 av1 = *reinterpret_cast<const float4*>(&As[buf][kk][ty * TM + 4]);
            float4 bv0 = *reinterpret_cast<const float4*>(&Bs[buf][kk][tx * TN]);
            float4 bv1 = *reinterpret_cast<const float4*>(&Bs[buf][kk][tx * TN + 4]);
            float a[TM] = {av0.x, av0.y, av0.z, av0.w, av1.x, av1.y, av1.z, av1.w};
            float b[TN] = {bv0.x, bv0.y, bv0.z, bv0.w, bv1.x, bv1.y, bv1.z, bv1.w};
#pragma unroll
            for (int m = 0; m < TM; ++m)
#pragma unroll
                for (int n = 0; n < TN; ++n)
                    acc[m][n] = fmaf(a[m], b[n], acc[m][n]);
        }

        if (kt + 1 < NKT) store_tile(buf ^ 1);
        __syncthreads();
    }

    // ---- epilogue: add per-blade bias, write out ----
    const int orow0 = bm * BM + ty * TM;
    const int ocol0 = bn * BN + tx * TN;
    const float* bptr = bias + kblk * D + ocol0;
    float bv[TN];
#pragma unroll
    for (int n = 0; n < TN; ++n) bv[n] = bptr[n];

#pragma unroll
    for (int m = 0; m < TM; ++m) {
        float4 o0, o1;
        o0.x = acc[m][0] + bv[0];
        o0.y = acc[m][1] + bv[1];
        o0.z = acc[m][2] + bv[2];
        o0.w = acc[m][3] + bv[3];
        o1.x = acc[m][4] + bv[4];
        o1.y = acc[m][5] + bv[5];
        o1.z = acc[m][6] + bv[6];
        o1.w = acc[m][7] + bv[7];
        float* optr = out + (size_t)(orow0 + m) * D + ocol0;
        *reinterpret_cast<float4*>(optr)     = o0;
        *reinterpret_cast<float4*>(optr + 4) = o1;
    }
}

extern "C" void kernel_launch(void* const* d_in, const int* in_sizes, int n_in,
                              void* d_out, int out_size)
{
    const float* X    = (const float*)d_in[0];   // [16384, 2048]
    const float* W    = (const float*)d_in[1];   // [2048, 16384]
    const float* bias = (const float*)d_in[2];   // [16384]
    float* out        = (float*)d_out;           // [16384, 2048]

    dim3 grid(2048 / BN, 16384 / BM);            // (16, 128)
    dim3 block(NTHREADS);
    ga_dense_gemm<<<grid, block>>>(X, W, bias, out);
}

// round 3
// speedup vs baseline: 2.0305x; 2.0305x over previous
#include <cuda_runtime.h>
#include <cstdint>

// ---------------------------------------------------------------------------
// GA (3,0,0) fused dense layer as one TF32 mma.sync GEMM (sm_103 base target;
// tcgen05 is unavailable because the harness compiles via compute_103 PTX):
//   out[k*B+b, d] = sum_j s(k,j) * ( X[i(k,j)*B+b, :] @ W[:, j*D+d] ) + bias[k*D+d]
// M=16384, N=2048, K=16384.  BM=128, BN=128, BK=16, 256 thr, warp tile 64x32.
// ---------------------------------------------------------------------------

#define NTHREADS 256
#define BK 16
#define NKT 1024            // 16384 / BK
#define ASTRIDE 20          // floats per A smem row  (conflict-free frag reads)
#define BSTRIDE 20          // floats per B smem row

// ---------------- Cayley table (validated in round 1) ----------------
__device__ __constant__ int c_kij[64] = {
    0,1,2,3,4,5,6,7,  1,0,4,5,2,3,7,6,  2,4,0,6,1,7,3,5,  3,5,6,0,7,1,2,4,
    4,2,1,7,0,6,5,3,  5,3,7,1,6,0,4,2,  6,7,3,2,5,4,0,1,  7,6,5,4,3,2,1,0};
__device__ __constant__ float c_sij[64] = {
    1.f, 1.f, 1.f, 1.f, 1.f, 1.f, 1.f, 1.f,
    1.f, 1.f, 1.f, 1.f, 1.f, 1.f, 1.f, 1.f,
    1.f,-1.f, 1.f, 1.f,-1.f,-1.f, 1.f,-1.f,
    1.f,-1.f,-1.f, 1.f, 1.f,-1.f,-1.f, 1.f,
    1.f,-1.f, 1.f, 1.f,-1.f,-1.f, 1.f,-1.f,
    1.f,-1.f,-1.f, 1.f, 1.f,-1.f,-1.f, 1.f,
    1.f, 1.f,-1.f, 1.f,-1.f, 1.f,-1.f,-1.f,
    1.f, 1.f,-1.f, 1.f,-1.f, 1.f,-1.f,-1.f};

__device__ __forceinline__ void gather_info(int kblk, int j, int& ib, float& sg) {
    int ibv = 0; float sv = 1.f;
#pragma unroll
    for (int ii = 0; ii < 8; ++ii) {
        bool m = (c_kij[ii * 8 + j] == kblk);
        ibv = m ? ii : ibv;
        sv  = m ? c_sij[ii * 8 + j] : sv;
    }
    ib = ibv; sg = sv;
}

__device__ __forceinline__ uint32_t f2tf32(float f) {
    uint32_t r;
    asm("cvt.rna.tf32.f32 %0, %1;" : "=r"(r) : "f"(f));
    return r;
}

__device__ __forceinline__ void mma_tf32(float* d, const uint32_t* a, const uint32_t* b) {
    asm volatile(
        "mma.sync.aligned.m16n8k8.row.col.f32.tf32.tf32.f32 "
        "{%0,%1,%2,%3}, {%4,%5,%6,%7}, {%8,%9}, {%0,%1,%2,%3};"
        : "+f"(d[0]), "+f"(d[1]), "+f"(d[2]), "+f"(d[3])
        : "r"(a[0]), "r"(a[1]), "r"(a[2]), "r"(a[3]), "r"(b[0]), "r"(b[1]));
}

// ---------------------------------------------------------------------------
__global__ __launch_bounds__(NTHREADS)
void ga_tf32_mma(const float* __restrict__ X,     // [16384, 2048]
                 const float* __restrict__ W,     // [2048, 16384]
                 const float* __restrict__ bias,  // [16384]
                 float* __restrict__ out)         // [16384, 2048]
{
    __shared__ uint32_t As[2][128 * ASTRIDE];   // [m][k], tf32 bits
    __shared__ uint32_t Bs[2][128 * BSTRIDE];   // [n][k], tf32 bits (transposed)

    const int tid  = threadIdx.x;
    const int wid  = tid >> 5;
    const int lane = tid & 31;
    const int q    = lane & 3;      // thread-in-group
    const int g    = lane >> 2;     // group id
    const int wm   = wid >> 2;      // 0..1  (M warps)
    const int wn   = wid & 3;       // 0..3  (N warps)

    const int bn   = blockIdx.x;    // 0..15  N tiles
    const int bm   = blockIdx.y;    // 0..127 M tiles
    const int kblk = bm >> 4;       // output blade
    const int rloc = (bm & 15) * 128;

    int   ibA[8];
    float sgA[8];
#pragma unroll
    for (int j = 0; j < 8; ++j) gather_info(kblk, j, ibA[j], sgA[j]);

    float acc[4][4][4];
#pragma unroll
    for (int f = 0; f < 4; ++f)
#pragma unroll
        for (int n = 0; n < 4; ++n)
#pragma unroll
            for (int e = 0; e < 4; ++e) acc[f][n][e] = 0.f;

    // gmem staging registers
    float4 ra[2], rb[2];
    float  rsg = 1.f;

    // A fill mapping: idx = tid + 256*i : m = idx/4, c4 = idx%4 (float4 along k)
    const int a_m  = tid >> 2;            // row for i=0 (0..63); +64 for i=1
    const int a_c  = (tid & 3) * 4;       // k offset
    // B fill mapping: idx = tid + 256*i : k = idx%16, n4 = idx/16 (float4 along n)
    const int b_k  = tid & 15;
    const int b_n4 = tid >> 4;            // 0..15 ; +16 for i=1

    auto ldg_tile = [&](int kt) {
        const int j  = kt >> 7;                 // 128 iters per j-block
        const int c0 = (kt & 127) * BK;
        rsg = sgA[j];
        const float* Ap = X + ((size_t)(ibA[j] * 2048 + rloc)) * 2048 + c0;
        ra[0] = *reinterpret_cast<const float4*>(Ap + (size_t)a_m * 2048 + a_c);
        ra[1] = *reinterpret_cast<const float4*>(Ap + (size_t)(a_m + 64) * 2048 + a_c);
        const float* Bp = W + (size_t)c0 * 16384 + (size_t)j * 2048 + (size_t)bn * 128;
        rb[0] = *reinterpret_cast<const float4*>(Bp + (size_t)b_k * 16384 + b_n4 * 4);
        rb[1] = *reinterpret_cast<const float4*>(Bp + (size_t)b_k * 16384 + (b_n4 + 16) * 4);
    };

    auto sts_tile = [&](int s) {
        // A: sign folded in, RN-rounded to tf32
        uint32_t* Ad = &As[s][0];
#pragma unroll
        for (int i = 0; i < 2; ++i) {
            const float4 v = ra[i];
            uint32_t* p = Ad + (a_m + i * 64) * ASTRIDE + a_c;
            p[0] = f2tf32(v.x * rsg); p[1] = f2tf32(v.y * rsg);
            p[2] = f2tf32(v.z * rsg); p[3] = f2tf32(v.w * rsg);
        }
        // B: transpose [k][n] -> [n][k]
        uint32_t* Bd = &Bs[s][0];
#pragma unroll
        for (int i = 0; i < 2; ++i) {
            const float4 v = rb[i];
            const int n0 = (b_n4 + i * 16) * 4;
            Bd[(n0 + 0) * BSTRIDE + b_k] = f2tf32(v.x);
            Bd[(n0 + 1) * BSTRIDE + b_k] = f2tf32(v.y);
            Bd[(n0 + 2) * BSTRIDE + b_k] = f2tf32(v.z);
            Bd[(n0 + 3) * BSTRIDE + b_k] = f2tf32(v.w);
        }
    };

    // prologue
    ldg_tile(0);
    sts_tile(0);
    __syncthreads();

    for (int kt = 0; kt < NKT; ++kt) {
        const int buf = kt & 1;
        if (kt + 1 < NKT) ldg_tile(kt + 1);

        const uint32_t* Ab = &As[buf][0];
        const uint32_t* Bb = &Bs[buf][0];

#pragma unroll
        for (int ks = 0; ks < 2; ++ks) {
            const int kq = ks * 8 + q;
            uint32_t afr[4][4], bfr[4][2];
#pragma unroll
            for (int f = 0; f < 4; ++f) {
                const int m0 = wm * 64 + f * 16 + g;
                afr[f][0] = Ab[(m0    ) * ASTRIDE + kq    ];
                afr[f][1] = Ab[(m0 + 8) * ASTRIDE + kq    ];
                afr[f][2] = Ab[(m0    ) * ASTRIDE + kq + 4];
                afr[f][3] = Ab[(m0 + 8) * ASTRIDE + kq + 4];
            }
#pragma unroll
            for (int n = 0; n < 4; ++n) {
                const int n0 = wn * 32 + n * 8 + g;
                bfr[n][0] = Bb[n0 * BSTRIDE + kq    ];
                bfr[n][1] = Bb[n0 * BSTRIDE + kq + 4];
            }
#pragma unroll
            for (int f = 0; f < 4; ++f)
#pragma unroll
                for (int n = 0; n < 4; ++n)
                    mma_tf32(acc[f][n], afr[f], bfr[n]);
        }

        if (kt + 1 < NKT) sts_tile(buf ^ 1);
        __syncthreads();
    }

    // ---- epilogue: add blade bias, store ----
    const int   crow = bm * 128 + wm * 64;
    const int   ccol = bn * 128 + wn * 32;
    const float* bp  = bias + (size_t)kblk * 2048 + ccol;

#pragma unroll
    for (int n = 0; n < 4; ++n) {
        const int cn = n * 8 + 2 * q;
        const float b0 = bp[cn], b1 = bp[cn + 1];
#pragma unroll
        for (int f = 0; f < 4; ++f) {
            const int r0 = crow + f * 16 + g;
            float2 lo = make_float2(acc[f][n][0] + b0, acc[f][n][1] + b1);
            float2 hi = make_float2(acc[f][n][2] + b0, acc[f][n][3] + b1);
            *reinterpret_cast<float2*>(out + (size_t)r0 * 2048 + ccol + cn)       = lo;
            *reinterpret_cast<float2*>(out + (size_t)(r0 + 8) * 2048 + ccol + cn) = hi;
        }
    }
}

extern "C" void kernel_launch(void* const* d_in, const int* in_sizes, int n_in,
                              void* d_out, int out_size)
{
    const float* X    = (const float*)d_in[0];
    const float* W    = (const float*)d_in[1];
    const float* bias = (const float*)d_in[2];
    float* out        = (float*)d_out;

    dim3 grid(16, 128);      // N tiles x M tiles
    dim3 block(NTHREADS);
    ga_tf32_mma<<<grid, block>>>(X, W, bias, out);
}

// round 4
// speedup vs baseline: 3.2074x; 1.5796x over previous
#include <cuda_runtime.h>
#include <cstdint>

// ---------------------------------------------------------------------------
// GA (3,0,0) fused dense layer as one TF32 mma.sync GEMM.
//   out[k*B+b, d] = sum_j s(k,j) * ( X[i(k,j)*B+b, :] @ W[:, j*D+d] ) + bias[k*D+d]
// M=16384, N=2048, K=16384.
// CTA tile 256x128, BK=16, 256 threads, 8 warps (4x2) of 64x64 warp tiles.
// A smem: [m][k] chunk-XOR swizzle (conflict-free STS.128 + frag LDS).
// B smem: [k][n] stride 168 (no transpose; conflict-free STS.128 + frag LDS).
// ---------------------------------------------------------------------------

#define NTHREADS 256
#define BK 16
#define NKT 1024              // 16384 / BK
#define ASZ 4096              // A words per stage: 256*16
#define BSTRIDE 168           // B words per k-row (128 + 40 pad, 16B-aligned, bank-magic 8)
#define BSZ (16 * BSTRIDE)    // 2688
#define STAGE_W (ASZ + BSZ)   // 6784 words
#define SMEM_BYTES (2 * STAGE_W * 4)

// ---------------- Cayley table (validated rounds 1/3) ----------------
__device__ __constant__ int c_kij[64] = {
    0,1,2,3,4,5,6,7,  1,0,4,5,2,3,7,6,  2,4,0,6,1,7,3,5,  3,5,6,0,7,1,2,4,
    4,2,1,7,0,6,5,3,  5,3,7,1,6,0,4,2,  6,7,3,2,5,4,0,1,  7,6,5,4,3,2,1,0};
__device__ __constant__ float c_sij[64] = {
    1.f, 1.f, 1.f, 1.f, 1.f, 1.f, 1.f, 1.f,
    1.f, 1.f, 1.f, 1.f, 1.f, 1.f, 1.f, 1.f,
    1.f,-1.f, 1.f, 1.f,-1.f,-1.f, 1.f,-1.f,
    1.f,-1.f,-1.f, 1.f, 1.f,-1.f,-1.f, 1.f,
    1.f,-1.f, 1.f, 1.f,-1.f,-1.f, 1.f,-1.f,
    1.f,-1.f,-1.f, 1.f, 1.f,-1.f,-1.f, 1.f,
    1.f, 1.f,-1.f, 1.f,-1.f, 1.f,-1.f,-1.f,
    1.f, 1.f,-1.f, 1.f,-1.f, 1.f,-1.f,-1.f};

__device__ __forceinline__ void gather_info(int kblk, int j, int& ib, float& sg) {
    int ibv = 0; float sv = 1.f;
#pragma unroll
    for (int ii = 0; ii < 8; ++ii) {
        bool m = (c_kij[ii * 8 + j] == kblk);
        ibv = m ? ii : ibv;
        sv  = m ? c_sij[ii * 8 + j] : sv;
    }
    ib = ibv; sg = sv;
}

__device__ __forceinline__ uint32_t f2tf32(float f) {
    uint32_t r;
    asm("cvt.rna.tf32.f32 %0, %1;" : "=r"(r) : "f"(f));
    return r;
}

__device__ __forceinline__ void mma_tf32(float* d, const uint32_t* a, const uint32_t* b) {
    asm volatile(
        "mma.sync.aligned.m16n8k8.row.col.f32.tf32.tf32.f32 "
        "{%0,%1,%2,%3}, {%4,%5,%6,%7}, {%8,%9}, {%0,%1,%2,%3};"
        : "+f"(d[0]), "+f"(d[1]), "+f"(d[2]), "+f"(d[3])
        : "r"(a[0]), "r"(a[1]), "r"(a[2]), "r"(a[3]), "r"(b[0]), "r"(b[1]));
}

// ---------------------------------------------------------------------------
__global__ __launch_bounds__(NTHREADS, 1)
void ga_tf32_mma2(const float* __restrict__ X,     // [16384, 2048]
                  const float* __restrict__ W,     // [2048, 16384]
                  const float* __restrict__ bias,  // [16384]
                  float* __restrict__ out)         // [16384, 2048]
{
    extern __shared__ uint32_t sm[];

    const int tid  = threadIdx.x;
    const int wid  = tid >> 5;
    const int lane = tid & 31;
    const int q    = lane & 3;
    const int g    = lane >> 2;
    const int wm   = wid >> 1;      // 0..3 (M warps, 64 rows each)
    const int wn   = wid & 1;       // 0..1 (N warps, 64 cols each)

    const int bn   = blockIdx.x;    // 0..15  N tiles (128 wide)
    const int bm   = blockIdx.y;    // 0..63  M tiles (256 tall)
    const int kblk = bm >> 3;       // output blade (2048/256 = 8 tiles per blade)
    const int rloc = (bm & 7) * 256;

    int   ibA[8];
    float sgA[8];
#pragma unroll
    for (int j = 0; j < 8; ++j) gather_info(kblk, j, ibA[j], sgA[j]);

    float acc[4][8][4];
#pragma unroll
    for (int f = 0; f < 4; ++f)
#pragma unroll
        for (int n = 0; n < 8; ++n)
#pragma unroll
            for (int e = 0; e < 4; ++e) acc[f][n][e] = 0.f;

    // LDG/STS thread mappings
    const int a_m = tid >> 2;        // A row base (+64*i), i=0..3
    const int a_c = tid & 3;         // A k-chunk (constant per thread)
    const int b_k = tid >> 5;        // B k-row base (+8*i), i=0..1
    const int b_n = (tid & 31) * 4;  // B col (float4)

    float4 ra[4], rb[2];
    float  rsg = 1.f;

    auto ldg_tile = [&](int kt) {
        const int j  = kt >> 7;                  // 128 iters per j-block
        const int c0 = (kt & 127) * BK;
        rsg = sgA[j];
        const float* Ap = X + ((size_t)(ibA[j] * 2048 + rloc)) * 2048 + c0 + a_c * 4;
#pragma unroll
        for (int i = 0; i < 4; ++i)
            ra[i] = *reinterpret_cast<const float4*>(Ap + (size_t)(a_m + 64 * i) * 2048);
        const float* Bp = W + (size_t)c0 * 16384 + (size_t)j * 2048 + bn * 128 + b_n;
#pragma unroll
        for (int i = 0; i < 2; ++i)
            rb[i] = *reinterpret_cast<const float4*>(Bp + (size_t)(b_k + 8 * i) * 16384);
    };

    auto sts_tile = [&](int s) {
        uint32_t* As = sm + s * STAGE_W;
        uint32_t* Bs = As + ASZ;
#pragma unroll
        for (int i = 0; i < 4; ++i) {
            const int m  = a_m + 64 * i;
            const int ch = a_c ^ ((m >> 1) & 3);
            uint4 v;
            v.x = f2tf32(ra[i].x * rsg); v.y = f2tf32(ra[i].y * rsg);
            v.z = f2tf32(ra[i].z * rsg); v.w = f2tf32(ra[i].w * rsg);
            *reinterpret_cast<uint4*>(As + m * 16 + ch * 4) = v;
        }
#pragma unroll
        for (int i = 0; i < 2; ++i) {
            uint4 v;
            v.x = f2tf32(rb[i].x); v.y = f2tf32(rb[i].y);
            v.z = f2tf32(rb[i].z); v.w = f2tf32(rb[i].w);
            *reinterpret_cast<uint4*>(Bs + (b_k + 8 * i) * BSTRIDE + b_n) = v;
        }
    };

    // prologue
    ldg_tile(0);
    sts_tile(0);
    __syncthreads();

    for (int kt = 0; kt < NKT; ++kt) {
        const int buf = kt & 1;
        if (kt + 1 < NKT) ldg_tile(kt + 1);

        const uint32_t* As = sm + buf * STAGE_W;
        const uint32_t* Bs = As + ASZ;

#pragma unroll
        for (int ks = 0; ks < 2; ++ks) {
            uint32_t afr[4][4], bfr[8][2];
#pragma unroll
            for (int f = 0; f < 4; ++f) {
                const int m0 = wm * 64 + f * 16 + g;
                const int m1 = m0 + 8;
                const int s0 = (m0 >> 1) & 3;           // == ((m1>>1)&3)
                const int cA = ((2 * ks    ) ^ s0) << 2;
                const int cB = ((2 * ks + 1) ^ s0) << 2;
                afr[f][0] = As[m0 * 16 + cA + q];
                afr[f][1] = As[m1 * 16 + cA + q];
                afr[f][2] = As[m0 * 16 + cB + q];
                afr[f][3] = As[m1 * 16 + cB + q];
            }
#pragma unroll
            for (int nf = 0; nf < 8; ++nf) {
                const int n0 = wn * 64 + nf * 8 + g;
                bfr[nf][0] = Bs[(ks * 8 + q    ) * BSTRIDE + n0];
                bfr[nf][1] = Bs[(ks * 8 + q + 4) * BSTRIDE + n0];
            }
#pragma unroll
            for (int f = 0; f < 4; ++f)
#pragma unroll
                for (int nf = 0; nf < 8; ++nf)
                    mma_tf32(acc[f][nf], afr[f], bfr[nf]);
        }

        if (kt + 1 < NKT) sts_tile(buf ^ 1);
        __syncthreads();
    }

    // ---- epilogue: add blade bias, store ----
    const int ccol = bn * 128 + wn * 64;
    const float* bp = bias + (size_t)kblk * 2048 + ccol;

#pragma unroll
    for (int nf = 0; nf < 8; ++nf) {
        const int cn = nf * 8 + 2 * q;
        const float b0 = bp[cn], b1 = bp[cn + 1];
#pragma unroll
        for (int f = 0; f < 4; ++f) {
            const int r0 = bm * 256 + wm * 64 + f * 16 + g;
            float2 lo = make_float2(acc[f][nf][0] + b0, acc[f][nf][1] + b1);
            float2 hi = make_float2(acc[f][nf][2] + b0, acc[f][nf][3] + b1);
            *reinterpret_cast<float2*>(out + (size_t)r0 * 2048 + ccol + cn)       = lo;
            *reinterpret_cast<float2*>(out + (size_t)(r0 + 8) * 2048 + ccol + cn) = hi;
        }
    }
}

extern "C" void kernel_launch(void* const* d_in, const int* in_sizes, int n_in,
                              void* d_out, int out_size)
{
    const float* X    = (const float*)d_in[0];
    const float* W    = (const float*)d_in[1];
    const float* bias = (const float*)d_in[2];
    float* out        = (float*)d_out;

    cudaFuncSetAttribute(ga_tf32_mma2, cudaFuncAttributeMaxDynamicSharedMemorySize, SMEM_BYTES);

    dim3 grid(16, 64);      // N tiles x M tiles
    dim3 block(NTHREADS);
    ga_tf32_mma2<<<grid, block, SMEM_BYTES>>>(X, W, bias, out);
}

// round 5
// speedup vs baseline: 3.5043x; 1.0926x over previous
#include <cuda_runtime.h>
#include <cstdint>

// ---------------------------------------------------------------------------
// GA (3,0,0) fused dense layer as one TF32 mma.sync GEMM.
//   out[k*B+b, d] = sum_j s(k,j) * ( X[i(k,j)*B+b, :] @ W[:, j*D+d] ) + bias[k*D+d]
// M=16384, N=2048, K=16384.
// R5: pre-round X/W to tf32 in gmem scratch; 4-stage cp.async pipeline;
//     signs applied by XOR on A fragments. CTA 256x128, warp tile 64x64.
// ---------------------------------------------------------------------------

#define NTHREADS 256
#define BK 16
#define NKT 1024               // 16384 / BK
#define ASZ 4096               // A words per stage: 256*16
#define BSTRIDE 168            // B words per k-row (128 + 40 pad)
#define BSZ (16 * BSTRIDE)     // 2688 words
#define STAGE_W (ASZ + BSZ)    // 6784 words
#define STAGES 4
#define SMEM_BYTES (STAGES * STAGE_W * 4)   // 108544

// 128 MB scratch each: tf32-rounded copies of X and W
__device__ float Xc[16384 * 2048];
__device__ float Wc[2048 * 16384];

// ---------------- Cayley table (validated rounds 1/3/4) ----------------
__device__ __constant__ int c_kij[64] = {
    0,1,2,3,4,5,6,7,  1,0,4,5,2,3,7,6,  2,4,0,6,1,7,3,5,  3,5,6,0,7,1,2,4,
    4,2,1,7,0,6,5,3,  5,3,7,1,6,0,4,2,  6,7,3,2,5,4,0,1,  7,6,5,4,3,2,1,0};
__device__ __constant__ float c_sij[64] = {
    1.f, 1.f, 1.f, 1.f, 1.f, 1.f, 1.f, 1.f,
    1.f, 1.f, 1.f, 1.f, 1.f, 1.f, 1.f, 1.f,
    1.f,-1.f, 1.f, 1.f,-1.f,-1.f, 1.f,-1.f,
    1.f,-1.f,-1.f, 1.f, 1.f,-1.f,-1.f, 1.f,
    1.f,-1.f, 1.f, 1.f,-1.f,-1.f, 1.f,-1.f,
    1.f,-1.f,-1.f, 1.f, 1.f,-1.f,-1.f, 1.f,
    1.f, 1.f,-1.f, 1.f,-1.f, 1.f,-1.f,-1.f,
    1.f, 1.f,-1.f, 1.f,-1.f, 1.f,-1.f,-1.f};

__device__ __forceinline__ void gather_info(int kblk, int j, int& ib, float& sg) {
    int ibv = 0; float sv = 1.f;
#pragma unroll
    for (int ii = 0; ii < 8; ++ii) {
        bool m = (c_kij[ii * 8 + j] == kblk);
        ibv = m ? ii : ibv;
        sv  = m ? c_sij[ii * 8 + j] : sv;
    }
    ib = ibv; sg = sv;
}

__device__ __forceinline__ uint32_t f2tf32(float f) {
    uint32_t r;
    asm("cvt.rna.tf32.f32 %0, %1;" : "=r"(r) : "f"(f));
    return r;
}

__device__ __forceinline__ void mma_tf32(float* d, const uint32_t* a, const uint32_t* b) {
    asm volatile(
        "mma.sync.aligned.m16n8k8.row.col.f32.tf32.tf32.f32 "
        "{%0,%1,%2,%3}, {%4,%5,%6,%7}, {%8,%9}, {%0,%1,%2,%3};"
        : "+f"(d[0]), "+f"(d[1]), "+f"(d[2]), "+f"(d[3])
        : "r"(a[0]), "r"(a[1]), "r"(a[2]), "r"(a[3]), "r"(b[0]), "r"(b[1]));
}

__device__ __forceinline__ uint32_t smem_u32(const void* p) {
    uint32_t a;
    asm("{ .reg .u64 t; cvta.to.shared.u64 t, %1; cvt.u32.u64 %0, t; }" : "=r"(a) : "l"(p));
    return a;
}

__device__ __forceinline__ void cp16(uint32_t dst, const float* src) {
    asm volatile("cp.async.cg.shared.global [%0], [%1], 16;" :: "r"(dst), "l"(src) : "memory");
}
#define CP_COMMIT()  asm volatile("cp.async.commit_group;" ::: "memory")
#define CP_WAIT(n)   asm volatile("cp.async.wait_group %0;" :: "n"(n) : "memory")

// ---------------------------------------------------------------------------
// Preprocess: round X and W to tf32 (RN) so the GEMM's HW truncation is exact.
__global__ __launch_bounds__(256)
void preconv_tf32(const float* __restrict__ X, const float* __restrict__ W)
{
    const size_t i = ((size_t)blockIdx.x * 256 + threadIdx.x) * 4;   // over 33554432 elems
    float4 x = *reinterpret_cast<const float4*>(X + i);
    x.x = __uint_as_float(f2tf32(x.x)); x.y = __uint_as_float(f2tf32(x.y));
    x.z = __uint_as_float(f2tf32(x.z)); x.w = __uint_as_float(f2tf32(x.w));
    *reinterpret_cast<float4*>(Xc + i) = x;
    float4 w = *reinterpret_cast<const float4*>(W + i);
    w.x = __uint_as_float(f2tf32(w.x)); w.y = __uint_as_float(f2tf32(w.y));
    w.z = __uint_as_float(f2tf32(w.z)); w.w = __uint_as_float(f2tf32(w.w));
    *reinterpret_cast<float4*>(Wc + i) = w;
}

// ---------------------------------------------------------------------------
__global__ __launch_bounds__(NTHREADS, 1)
void ga_tf32_mma3(const float* __restrict__ bias,  // [16384]
                  float* __restrict__ out)         // [16384, 2048]
{
    extern __shared__ uint32_t sm[];
    const uint32_t sb = smem_u32(sm);

    const int tid  = threadIdx.x;
    const int wid  = tid >> 5;
    const int lane = tid & 31;
    const int q    = lane & 3;
    const int g    = lane >> 2;
    const int wm   = wid >> 1;      // 0..3 (M warps, 64 rows each)
    const int wn   = wid & 1;       // 0..1 (N warps, 64 cols each)

    const int bn   = blockIdx.x;    // 0..15  N tiles (128 wide)
    const int bm   = blockIdx.y;    // 0..63  M tiles (256 tall)
    const int kblk = bm >> 3;       // output blade
    const int rloc = (bm & 7) * 256;

    int      ibA[8];
    uint32_t signbits = 0;
#pragma unroll
    for (int j = 0; j < 8; ++j) {
        int ib; float sg;
        gather_info(kblk, j, ib, sg);
        ibA[j] = ib;
        if (sg < 0.f) signbits |= (1u << j);
    }

    float acc[4][8][4];
#pragma unroll
    for (int f = 0; f < 4; ++f)
#pragma unroll
        for (int n = 0; n < 8; ++n)
#pragma unroll
            for (int e = 0; e < 4; ++e) acc[f][n][e] = 0.f;

    // copy thread mappings (same geometry as round 4)
    const int a_m = tid >> 2;        // A row base (+64*i), i=0..3
    const int a_c = tid & 3;         // A k-chunk
    const int b_k = tid >> 5;        // B k-row base (+8*i), i=0..1
    const int b_n = (tid & 31) * 4;  // B col (float4)

    // ---- issue cp.async for tile kt into stage s ----
    auto issue_tile = [&](int kt, int s) {
        const int j  = kt >> 7;
        const int c0 = (kt & 127) * BK;
        const uint32_t As = sb + (uint32_t)(s * STAGE_W * 4);
        const uint32_t Bs = As + ASZ * 4;
        const float* Ap = Xc + ((size_t)(ibA[j] * 2048 + rloc)) * 2048 + c0 + a_c * 4;
#pragma unroll
        for (int i = 0; i < 4; ++i) {
            const int m  = a_m + 64 * i;
            const int ch = a_c ^ ((m >> 1) & 3);
            cp16(As + (uint32_t)((m * 16 + ch * 4) * 4), Ap + (size_t)m * 2048);
        }
        const float* Bp = Wc + (size_t)c0 * 16384 + (size_t)j * 2048 + bn * 128 + b_n;
#pragma unroll
        for (int i = 0; i < 2; ++i)
            cp16(Bs + (uint32_t)(((b_k + 8 * i) * BSTRIDE + b_n) * 4),
                 Bp + (size_t)(b_k + 8 * i) * 16384);
    };

    // prologue: stages 0..2
#pragma unroll
    for (int s = 0; s < STAGES - 1; ++s) { issue_tile(s, s); CP_COMMIT(); }

    for (int kt = 0; kt < NKT; ++kt) {
        // tail-aware wait: guarantee tile kt's group is complete
        if (kt < NKT - 3)       { CP_WAIT(2); }
        else if (kt == NKT - 3) { CP_WAIT(2); }
        else if (kt == NKT - 2) { CP_WAIT(1); }
        else                    { CP_WAIT(0); }
        __syncthreads();

        if (kt + 3 < NKT) { issue_tile(kt + 3, (kt + 3) & 3); CP_COMMIT(); }

        const uint32_t* As = sm + (kt & 3) * STAGE_W;
        const uint32_t* Bs = As + ASZ;
        const uint32_t  smask = ((signbits >> (kt >> 7)) & 1u) << 31;

#pragma unroll
        for (int ks = 0; ks < 2; ++ks) {
            uint32_t afr[4][4], bfr[8][2];
#pragma unroll
            for (int f = 0; f < 4; ++f) {
                const int m0 = wm * 64 + f * 16 + g;
                const int m1 = m0 + 8;
                const int s0 = (m0 >> 1) & 3;
                const int cA = ((2 * ks    ) ^ s0) << 2;
                const int cB = ((2 * ks + 1) ^ s0) << 2;
                afr[f][0] = As[m0 * 16 + cA + q] ^ smask;
                afr[f][1] = As[m1 * 16 + cA + q] ^ smask;
                afr[f][2] = As[m0 * 16 + cB + q] ^ smask;
                afr[f][3] = As[m1 * 16 + cB + q] ^ smask;
            }
#pragma unroll
            for (int nf = 0; nf < 8; ++nf) {
                const int n0 = wn * 64 + nf * 8 + g;
                bfr[nf][0] = Bs[(ks * 8 + q    ) * BSTRIDE + n0];
                bfr[nf][1] = Bs[(ks * 8 + q + 4) * BSTRIDE + n0];
            }
#pragma unroll
            for (int f = 0; f < 4; ++f)
#pragma unroll
                for (int nf = 0; nf < 8; ++nf)
                    mma_tf32(acc[f][nf], afr[f], bfr[nf]);
        }
        __syncthreads();
    }

    // ---- epilogue: add blade bias, store ----
    const int ccol = bn * 128 + wn * 64;
    const float* bp = bias + (size_t)kblk * 2048 + ccol;

#pragma unroll
    for (int nf = 0; nf < 8; ++nf) {
        const int cn = nf * 8 + 2 * q;
        const float b0 = bp[cn], b1 = bp[cn + 1];
#pragma unroll
        for (int f = 0; f < 4; ++f) {
            const int r0 = bm * 256 + wm * 64 + f * 16 + g;
            float2 lo = make_float2(acc[f][nf][0] + b0, acc[f][nf][1] + b1);
            float2 hi = make_float2(acc[f][nf][2] + b0, acc[f][nf][3] + b1);
            *reinterpret_cast<float2*>(out + (size_t)r0 * 2048 + ccol + cn)       = lo;
            *reinterpret_cast<float2*>(out + (size_t)(r0 + 8) * 2048 + ccol + cn) = hi;
        }
    }
}

extern "C" void kernel_launch(void* const* d_in, const int* in_sizes, int n_in,
                              void* d_out, int out_size)
{
    const float* X    = (const float*)d_in[0];
    const float* W    = (const float*)d_in[1];
    const float* bias = (const float*)d_in[2];
    float* out        = (float*)d_out;

    // 1) round X, W to tf32 into scratch (33554432 elems each; 4/thread)
    preconv_tf32<<<32768, 256>>>(X, W);

    // 2) fused GA GEMM
    cudaFuncSetAttribute(ga_tf32_mma3, cudaFuncAttributeMaxDynamicSharedMemorySize, SMEM_BYTES);
    dim3 grid(16, 64);
    ga_tf32_mma3<<<grid, NTHREADS, SMEM_BYTES>>>(bias, out);
}

// round 6
// speedup vs baseline: 3.8025x; 1.0851x over previous
#include <cuda_runtime.h>
#include <cstdint>

// ---------------------------------------------------------------------------
// GA (3,0,0) fused dense layer as one TF32 mma.sync GEMM.
//   out[k*B+b, d] = sum_j s(k,j) * ( X[i(k,j)*B+b, :] @ W[:, j*D+d] ) + bias[k*D+d]
// M=16384, N=2048, K=16384.
// R6: 6-stage cp.async ring, ONE barrier per 2 k-tiles (pair-processed),
//     no trailing barrier. CTA 256x128, warp tile 64x64, signs via frag XOR.
// ---------------------------------------------------------------------------

#define NTHREADS 256
#define BK 16
#define NKT 1024               // 16384 / BK
#define NPAIRS 512
#define ASZ 4096               // A words per stage: 256*16
#define BSTRIDE 168            // B words per k-row (128 + 40 pad)
#define BSZ (16 * BSTRIDE)     // 2688 words
#define STAGE_W (ASZ + BSZ)    // 6784 words
#define STAGES 6
#define SMEM_BYTES (STAGES * STAGE_W * 4)   // 162816

// 128 MB scratch each: tf32-rounded copies of X and W
__device__ float Xc[16384 * 2048];
__device__ float Wc[2048 * 16384];

// ---------------- Cayley table (validated rounds 1/3/4/5) ----------------
__device__ __constant__ int c_kij[64] = {
    0,1,2,3,4,5,6,7,  1,0,4,5,2,3,7,6,  2,4,0,6,1,7,3,5,  3,5,6,0,7,1,2,4,
    4,2,1,7,0,6,5,3,  5,3,7,1,6,0,4,2,  6,7,3,2,5,4,0,1,  7,6,5,4,3,2,1,0};
__device__ __constant__ float c_sij[64] = {
    1.f, 1.f, 1.f, 1.f, 1.f, 1.f, 1.f, 1.f,
    1.f, 1.f, 1.f, 1.f, 1.f, 1.f, 1.f, 1.f,
    1.f,-1.f, 1.f, 1.f,-1.f,-1.f, 1.f,-1.f,
    1.f,-1.f,-1.f, 1.f, 1.f,-1.f,-1.f, 1.f,
    1.f,-1.f, 1.f, 1.f,-1.f,-1.f, 1.f,-1.f,
    1.f,-1.f,-1.f, 1.f, 1.f,-1.f,-1.f, 1.f,
    1.f, 1.f,-1.f, 1.f,-1.f, 1.f,-1.f,-1.f,
    1.f, 1.f,-1.f, 1.f,-1.f, 1.f,-1.f,-1.f};

__device__ __forceinline__ void gather_info(int kblk, int j, int& ib, float& sg) {
    int ibv = 0; float sv = 1.f;
#pragma unroll
    for (int ii = 0; ii < 8; ++ii) {
        bool m = (c_kij[ii * 8 + j] == kblk);
        ibv = m ? ii : ibv;
        sv  = m ? c_sij[ii * 8 + j] : sv;
    }
    ib = ibv; sg = sv;
}

__device__ __forceinline__ uint32_t f2tf32(float f) {
    uint32_t r;
    asm("cvt.rna.tf32.f32 %0, %1;" : "=r"(r) : "f"(f));
    return r;
}

__device__ __forceinline__ void mma_tf32(float* d, const uint32_t* a, const uint32_t* b) {
    asm volatile(
        "mma.sync.aligned.m16n8k8.row.col.f32.tf32.tf32.f32 "
        "{%0,%1,%2,%3}, {%4,%5,%6,%7}, {%8,%9}, {%0,%1,%2,%3};"
        : "+f"(d[0]), "+f"(d[1]), "+f"(d[2]), "+f"(d[3])
        : "r"(a[0]), "r"(a[1]), "r"(a[2]), "r"(a[3]), "r"(b[0]), "r"(b[1]));
}

__device__ __forceinline__ uint32_t smem_u32(const void* p) {
    uint32_t a;
    asm("{ .reg .u64 t; cvta.to.shared.u64 t, %1; cvt.u32.u64 %0, t; }" : "=r"(a) : "l"(p));
    return a;
}

__device__ __forceinline__ void cp16(uint32_t dst, const float* src) {
    asm volatile("cp.async.cg.shared.global [%0], [%1], 16;" :: "r"(dst), "l"(src) : "memory");
}
#define CP_COMMIT()  asm volatile("cp.async.commit_group;" ::: "memory")
#define CP_WAIT(n)   asm volatile("cp.async.wait_group %0;" :: "n"(n) : "memory")

// ---------------------------------------------------------------------------
// Preprocess: round X and W to tf32 (RN) so the GEMM's HW truncation is exact.
__global__ __launch_bounds__(256)
void preconv_tf32(const float* __restrict__ X, const float* __restrict__ W)
{
    const size_t i = ((size_t)blockIdx.x * 256 + threadIdx.x) * 4;
    float4 x = *reinterpret_cast<const float4*>(X + i);
    x.x = __uint_as_float(f2tf32(x.x)); x.y = __uint_as_float(f2tf32(x.y));
    x.z = __uint_as_float(f2tf32(x.z)); x.w = __uint_as_float(f2tf32(x.w));
    *reinterpret_cast<float4*>(Xc + i) = x;
    float4 w = *reinterpret_cast<const float4*>(W + i);
    w.x = __uint_as_float(f2tf32(w.x)); w.y = __uint_as_float(f2tf32(w.y));
    w.z = __uint_as_float(f2tf32(w.z)); w.w = __uint_as_float(f2tf32(w.w));
    *reinterpret_cast<float4*>(Wc + i) = w;
}

// ---------------------------------------------------------------------------
__global__ __launch_bounds__(NTHREADS, 1)
void ga_tf32_mma4(const float* __restrict__ bias,  // [16384]
                  float* __restrict__ out)         // [16384, 2048]
{
    extern __shared__ uint32_t sm[];
    const uint32_t sb = smem_u32(sm);

    const int tid  = threadIdx.x;
    const int wid  = tid >> 5;
    const int lane = tid & 31;
    const int q    = lane & 3;
    const int g    = lane >> 2;
    const int wm   = wid >> 1;      // 0..3 (M warps, 64 rows each)
    const int wn   = wid & 1;       // 0..1 (N warps, 64 cols each)

    const int bn   = blockIdx.x;    // 0..15  N tiles (128 wide)
    const int bm   = blockIdx.y;    // 0..63  M tiles (256 tall)
    const int kblk = bm >> 3;       // output blade
    const int rloc = (bm & 7) * 256;

    int      ibA[8];
    uint32_t signbits = 0;
#pragma unroll
    for (int j = 0; j < 8; ++j) {
        int ib; float sg;
        gather_info(kblk, j, ib, sg);
        ibA[j] = ib;
        if (sg < 0.f) signbits |= (1u << j);
    }

    float acc[4][8][4];
#pragma unroll
    for (int f = 0; f < 4; ++f)
#pragma unroll
        for (int n = 0; n < 8; ++n)
#pragma unroll
            for (int e = 0; e < 4; ++e) acc[f][n][e] = 0.f;

    // copy thread mappings (geometry identical to rounds 4/5)
    const int a_m = tid >> 2;
    const int a_c = tid & 3;
    const int b_k = tid >> 5;
    const int b_n = (tid & 31) * 4;

    auto issue_tile = [&](int kt) {
        const int s  = kt % STAGES;
        const int j  = kt >> 7;
        const int c0 = (kt & 127) * BK;
        const uint32_t As = sb + (uint32_t)(s * STAGE_W * 4);
        const uint32_t Bs = As + ASZ * 4;
        const float* Ap = Xc + ((size_t)(ibA[j] * 2048 + rloc)) * 2048 + c0 + a_c * 4;
#pragma unroll
        for (int i = 0; i < 4; ++i) {
            const int m  = a_m + 64 * i;
            const int ch = a_c ^ ((m >> 1) & 3);
            cp16(As + (uint32_t)((m * 16 + ch * 4) * 4), Ap + (size_t)m * 2048);
        }
        const float* Bp = Wc + (size_t)c0 * 16384 + (size_t)j * 2048 + bn * 128 + b_n;
#pragma unroll
        for (int i = 0; i < 2; ++i)
            cp16(Bs + (uint32_t)(((b_k + 8 * i) * BSTRIDE + b_n) * 4),
                 Bp + (size_t)(b_k + 8 * i) * 16384);
    };

    // ---- compute one k-tile from its smem stage ----
    auto compute_tile = [&](int kt) {
        const uint32_t* As = sm + (kt % STAGES) * STAGE_W;
        const uint32_t* Bs = As + ASZ;
        const uint32_t  smask = ((signbits >> (kt >> 7)) & 1u) << 31;
#pragma unroll
        for (int ks = 0; ks < 2; ++ks) {
            uint32_t afr[4][4], bfr[8][2];
#pragma unroll
            for (int f = 0; f < 4; ++f) {
                const int m0 = wm * 64 + f * 16 + g;
                const int m1 = m0 + 8;
                const int s0 = (m0 >> 1) & 3;
                const int cA = ((2 * ks    ) ^ s0) << 2;
                const int cB = ((2 * ks + 1) ^ s0) << 2;
                afr[f][0] = As[m0 * 16 + cA + q] ^ smask;
                afr[f][1] = As[m1 * 16 + cA + q] ^ smask;
                afr[f][2] = As[m0 * 16 + cB + q] ^ smask;
                afr[f][3] = As[m1 * 16 + cB + q] ^ smask;
            }
#pragma unroll
            for (int nf = 0; nf < 8; ++nf) {
                const int n0 = wn * 64 + nf * 8 + g;
                bfr[nf][0] = Bs[(ks * 8 + q    ) * BSTRIDE + n0];
                bfr[nf][1] = Bs[(ks * 8 + q + 4) * BSTRIDE + n0];
            }
#pragma unroll
            for (int f = 0; f < 4; ++f)
#pragma unroll
                for (int nf = 0; nf < 8; ++nf)
                    mma_tf32(acc[f][nf], afr[f], bfr[nf]);
        }
    };

    // prologue: pairs 0 and 1 (tiles 0..3), one commit group per pair
    issue_tile(0); issue_tile(1); CP_COMMIT();
    issue_tile(2); issue_tile(3); CP_COMMIT();

    for (int p = 0; p < NPAIRS; ++p) {
        if (p < NPAIRS - 1) { CP_WAIT(1); } else { CP_WAIT(0); }
        __syncthreads();     // single barrier per pair; protects stage reuse

        if (p + 2 < NPAIRS) {
            issue_tile(2 * p + 4);
            issue_tile(2 * p + 5);
            CP_COMMIT();
        }

        compute_tile(2 * p);
        compute_tile(2 * p + 1);
        // no trailing barrier: next iteration's writes target the stages of
        // pair p-1, which every warp finished before this iteration's barrier.
    }

    // ---- epilogue: add blade bias, store ----
    const int ccol = bn * 128 + wn * 64;
    const float* bp = bias + (size_t)kblk * 2048 + ccol;

#pragma unroll
    for (int nf = 0; nf < 8; ++nf) {
        const int cn = nf * 8 + 2 * q;
        const float b0 = bp[cn], b1 = bp[cn + 1];
#pragma unroll
        for (int f = 0; f < 4; ++f) {
            const int r0 = bm * 256 + wm * 64 + f * 16 + g;
            float2 lo = make_float2(acc[f][nf][0] + b0, acc[f][nf][1] + b1);
            float2 hi = make_float2(acc[f][nf][2] + b0, acc[f][nf][3] + b1);
            *reinterpret_cast<float2*>(out + (size_t)r0 * 2048 + ccol + cn)       = lo;
            *reinterpret_cast<float2*>(out + (size_t)(r0 + 8) * 2048 + ccol + cn) = hi;
        }
    }
}

extern "C" void kernel_launch(void* const* d_in, const int* in_sizes, int n_in,
                              void* d_out, int out_size)
{
    const float* X    = (const float*)d_in[0];
    const float* W    = (const float*)d_in[1];
    const float* bias = (const float*)d_in[2];
    float* out        = (float*)d_out;

    preconv_tf32<<<32768, 256>>>(X, W);

    cudaFuncSetAttribute(ga_tf32_mma4, cudaFuncAttributeMaxDynamicSharedMemorySize, SMEM_BYTES);
    dim3 grid(16, 64);
    ga_tf32_mma4<<<grid, NTHREADS, SMEM_BYTES>>>(bias, out);
}

// round 7
// speedup vs baseline: 4.2046x; 1.1057x over previous
#include <cuda_runtime.h>
#include <cstdint>

// ---------------------------------------------------------------------------
// GA (3,0,0) fused dense layer as one TF32 mma.sync GEMM.
//   out[k*B+b, d] = sum_j s(k,j) * ( X[i(k,j)*B+b, :] @ W[:, j*D+d] ) + bias[k*D+d]
// M=16384, N=2048, K=16384.
// R7: CTA 128x128 / 128 threads, 2 CTAs/SM; ldmatrix.x4 for A fragments;
//     6-stage cp.async ring, one barrier per 2 k-tiles; signs via frag XOR.
// ---------------------------------------------------------------------------

#define NTHREADS 128
#define BK 16
#define NKT 1024               // 16384 / BK
#define NPAIRS 512
#define ASZ 2048               // A words per stage: 128*16
#define BSTRIDE 168            // B words per k-row (128 + 40 pad)
#define BSZ (16 * BSTRIDE)     // 2688 words
#define STAGE_W (ASZ + BSZ)    // 4736 words = 18944 B
#define STAGES 6
#define SMEM_BYTES (STAGES * STAGE_W * 4)   // 113664 B per CTA

// 128 MB scratch each: tf32-rounded copies of X and W
__device__ float Xc[16384 * 2048];
__device__ float Wc[2048 * 16384];

// ---------------- Cayley table (validated rounds 1/3/4/5/6) ----------------
__device__ __constant__ int c_kij[64] = {
    0,1,2,3,4,5,6,7,  1,0,4,5,2,3,7,6,  2,4,0,6,1,7,3,5,  3,5,6,0,7,1,2,4,
    4,2,1,7,0,6,5,3,  5,3,7,1,6,0,4,2,  6,7,3,2,5,4,0,1,  7,6,5,4,3,2,1,0};
__device__ __constant__ float c_sij[64] = {
    1.f, 1.f, 1.f, 1.f, 1.f, 1.f, 1.f, 1.f,
    1.f, 1.f, 1.f, 1.f, 1.f, 1.f, 1.f, 1.f,
    1.f,-1.f, 1.f, 1.f,-1.f,-1.f, 1.f,-1.f,
    1.f,-1.f,-1.f, 1.f, 1.f,-1.f,-1.f, 1.f,
    1.f,-1.f, 1.f, 1.f,-1.f,-1.f, 1.f,-1.f,
    1.f,-1.f,-1.f, 1.f, 1.f,-1.f,-1.f, 1.f,
    1.f, 1.f,-1.f, 1.f,-1.f, 1.f,-1.f,-1.f,
    1.f, 1.f,-1.f, 1.f,-1.f, 1.f,-1.f,-1.f};

__device__ __forceinline__ void gather_info(int kblk, int j, int& ib, float& sg) {
    int ibv = 0; float sv = 1.f;
#pragma unroll
    for (int ii = 0; ii < 8; ++ii) {
        bool m = (c_kij[ii * 8 + j] == kblk);
        ibv = m ? ii : ibv;
        sv  = m ? c_sij[ii * 8 + j] : sv;
    }
    ib = ibv; sg = sv;
}

__device__ __forceinline__ uint32_t f2tf32(float f) {
    uint32_t r;
    asm("cvt.rna.tf32.f32 %0, %1;" : "=r"(r) : "f"(f));
    return r;
}

__device__ __forceinline__ void mma_tf32(float* d, const uint32_t* a, const uint32_t* b) {
    asm volatile(
        "mma.sync.aligned.m16n8k8.row.col.f32.tf32.tf32.f32 "
        "{%0,%1,%2,%3}, {%4,%5,%6,%7}, {%8,%9}, {%0,%1,%2,%3};"
        : "+f"(d[0]), "+f"(d[1]), "+f"(d[2]), "+f"(d[3])
        : "r"(a[0]), "r"(a[1]), "r"(a[2]), "r"(a[3]), "r"(b[0]), "r"(b[1]));
}

__device__ __forceinline__ void ldsm4(uint32_t* r, uint32_t addr) {
    asm volatile("ldmatrix.sync.aligned.m8n8.x4.shared.b16 {%0,%1,%2,%3}, [%4];"
        : "=r"(r[0]), "=r"(r[1]), "=r"(r[2]), "=r"(r[3]) : "r"(addr));
}

__device__ __forceinline__ uint32_t smem_u32(const void* p) {
    uint32_t a;
    asm("{ .reg .u64 t; cvta.to.shared.u64 t, %1; cvt.u32.u64 %0, t; }" : "=r"(a) : "l"(p));
    return a;
}

__device__ __forceinline__ void cp16(uint32_t dst, const float* src) {
    asm volatile("cp.async.cg.shared.global [%0], [%1], 16;" :: "r"(dst), "l"(src) : "memory");
}
#define CP_COMMIT()  asm volatile("cp.async.commit_group;" ::: "memory")
#define CP_WAIT(n)   asm volatile("cp.async.wait_group %0;" :: "n"(n) : "memory")

// ---------------------------------------------------------------------------
// Preprocess: round X and W to tf32 (RN) so the GEMM's HW truncation is exact.
__global__ __launch_bounds__(256)
void preconv_tf32(const float* __restrict__ X, const float* __restrict__ W)
{
    const size_t i = ((size_t)blockIdx.x * 256 + threadIdx.x) * 4;
    float4 x = *reinterpret_cast<const float4*>(X + i);
    x.x = __uint_as_float(f2tf32(x.x)); x.y = __uint_as_float(f2tf32(x.y));
    x.z = __uint_as_float(f2tf32(x.z)); x.w = __uint_as_float(f2tf32(x.w));
    *reinterpret_cast<float4*>(Xc + i) = x;
    float4 w = *reinterpret_cast<const float4*>(W + i);
    w.x = __uint_as_float(f2tf32(w.x)); w.y = __uint_as_float(f2tf32(w.y));
    w.z = __uint_as_float(f2tf32(w.z)); w.w = __uint_as_float(f2tf32(w.w));
    *reinterpret_cast<float4*>(Wc + i) = w;
}

// ---------------------------------------------------------------------------
__global__ __launch_bounds__(NTHREADS, 2)
void ga_tf32_mma5(const float* __restrict__ bias,  // [16384]
                  float* __restrict__ out)         // [16384, 2048]
{
    extern __shared__ uint32_t sm[];
    const uint32_t sb = smem_u32(sm);

    const int tid  = threadIdx.x;
    const int wid  = tid >> 5;
    const int lane = tid & 31;
    const int q    = lane & 3;
    const int g    = lane >> 2;
    const int wm   = wid >> 1;      // 0..1 (M warps, 64 rows each)
    const int wn   = wid & 1;       // 0..1 (N warps, 64 cols each)

    const int bn   = blockIdx.x;    // 0..15  N tiles (128 wide)
    const int bm   = blockIdx.y;    // 0..127 M tiles (128 tall)
    const int kblk = bm >> 4;       // output blade (2048/128 = 16 tiles per blade)
    const int rloc = (bm & 15) * 128;

    int      ibA[8];
    uint32_t signbits = 0;
#pragma unroll
    for (int j = 0; j < 8; ++j) {
        int ib; float sg;
        gather_info(kblk, j, ib, sg);
        ibA[j] = ib;
        if (sg < 0.f) signbits |= (1u << j);
    }

    float acc[4][8][4];
#pragma unroll
    for (int f = 0; f < 4; ++f)
#pragma unroll
        for (int n = 0; n < 8; ++n)
#pragma unroll
            for (int e = 0; e < 4; ++e) acc[f][n][e] = 0.f;

    // ---- ldmatrix per-lane address precompute (A fragments) ----
    // x4 matrices: sub 0: rows m0..m0+7 chunk lo | sub 1: rows +8 chunk lo
    //              sub 2: rows m0..m0+7 chunk hi | sub 3: rows +8 chunk hi
    const int sub    = lane >> 3;
    const int hi     = sub >> 1;                        // 0 = k[0..3], 1 = k[4..7] chunk
    const int rowoff = (lane & 7) + (sub & 1) * 8;
    uint32_t rbyte[4];  // per f: row byte offset within A stage
    int      sx[4];     // per f: swizzle term of that row
#pragma unroll
    for (int f = 0; f < 4; ++f) {
        const int r = wm * 64 + f * 16 + rowoff;
        rbyte[f] = (uint32_t)(r * 64);
        sx[f]    = (r >> 1) & 3;
    }

    // cp.async thread mappings
    const int a_m = tid >> 2;        // 0..31 (+32*i)
    const int a_c = tid & 3;
    const int b_k = tid >> 5;        // 0..3  (+4*i)
    const int b_n = (tid & 31) * 4;

    auto issue_tile = [&](int kt) {
        const int s  = kt % STAGES;
        const int j  = kt >> 7;
        const int c0 = (kt & 127) * BK;
        const uint32_t As = sb + (uint32_t)(s * STAGE_W * 4);
        const uint32_t Bs = As + ASZ * 4;
        const float* Ap = Xc + ((size_t)(ibA[j] * 2048 + rloc)) * 2048 + c0 + a_c * 4;
#pragma unroll
        for (int i = 0; i < 4; ++i) {
            const int m  = a_m + 32 * i;
            const int ch = a_c ^ ((m >> 1) & 3);
            cp16(As + (uint32_t)((m * 16 + ch * 4) * 4), Ap + (size_t)m * 2048);
        }
        const float* Bp = Wc + (size_t)c0 * 16384 + (size_t)j * 2048 + bn * 128 + b_n;
#pragma unroll
        for (int i = 0; i < 4; ++i)
            cp16(Bs + (uint32_t)(((b_k + 4 * i) * BSTRIDE + b_n) * 4),
                 Bp + (size_t)(b_k + 4 * i) * 16384);
    };

    auto compute_tile = [&](int kt) {
        const int s = kt % STAGES;
        const uint32_t AsAddr = sb + (uint32_t)(s * STAGE_W * 4);
        const uint32_t* Bs = sm + s * STAGE_W + ASZ;
        const uint32_t  smask = ((signbits >> (kt >> 7)) & 1u) << 31;
#pragma unroll
        for (int ks = 0; ks < 2; ++ks) {
            uint32_t afr[4][4], bfr[8][2];
#pragma unroll
            for (int f = 0; f < 4; ++f) {
                const int ch = (2 * ks + hi) ^ sx[f];
                ldsm4(afr[f], AsAddr + rbyte[f] + (uint32_t)(ch * 16));
            }
#pragma unroll
            for (int f = 0; f < 4; ++f) {
                afr[f][0] ^= smask; afr[f][1] ^= smask;
                afr[f][2] ^= smask; afr[f][3] ^= smask;
            }
#pragma unroll
            for (int nf = 0; nf < 8; ++nf) {
                const int n0 = wn * 64 + nf * 8 + g;
                bfr[nf][0] = Bs[(ks * 8 + q    ) * BSTRIDE + n0];
                bfr[nf][1] = Bs[(ks * 8 + q + 4) * BSTRIDE + n0];
            }
#pragma unroll
            for (int f = 0; f < 4; ++f)
#pragma unroll
                for (int nf = 0; nf < 8; ++nf)
                    mma_tf32(acc[f][nf], afr[f], bfr[nf]);
        }
    };

    // prologue: pairs 0 and 1 (tiles 0..3), one commit group per pair
    issue_tile(0); issue_tile(1); CP_COMMIT();
    issue_tile(2); issue_tile(3); CP_COMMIT();

    for (int p = 0; p < NPAIRS; ++p) {
        if (p < NPAIRS - 1) { CP_WAIT(1); } else { CP_WAIT(0); }
        __syncthreads();     // single barrier per pair; protects stage reuse

        if (p + 2 < NPAIRS) {
            issue_tile(2 * p + 4);
            issue_tile(2 * p + 5);
            CP_COMMIT();
        }

        compute_tile(2 * p);
        compute_tile(2 * p + 1);
        // no trailing barrier: next iteration's writes target pair p-1's
        // stages, which every warp finished before this iteration's barrier.
    }

    // ---- epilogue: add blade bias, store ----
    const int ccol = bn * 128 + wn * 64;
    const float* bp = bias + (size_t)kblk * 2048 + ccol;

#pragma unroll
    for (int nf = 0; nf < 8; ++nf) {
        const int cn = nf * 8 + 2 * q;
        const float b0 = bp[cn], b1 = bp[cn + 1];
#pragma unroll
        for (int f = 0; f < 4; ++f) {
            const int r0 = bm * 128 + wm * 64 + f * 16 + g;
            float2 lo = make_float2(acc[f][nf][0] + b0, acc[f][nf][1] + b1);
            float2 hi2 = make_float2(acc[f][nf][2] + b0, acc[f][nf][3] + b1);
            *reinterpret_cast<float2*>(out + (size_t)r0 * 2048 + ccol + cn)       = lo;
            *reinterpret_cast<float2*>(out + (size_t)(r0 + 8) * 2048 + ccol + cn) = hi2;
        }
    }
}

extern "C" void kernel_launch(void* const* d_in, const int* in_sizes, int n_in,
                              void* d_out, int out_size)
{
    const float* X    = (const float*)d_in[0];
    const float* W    = (const float*)d_in[1];
    const float* bias = (const float*)d_in[2];
    float* out        = (float*)d_out;

    preconv_tf32<<<32768, 256>>>(X, W);

    cudaFuncSetAttribute(ga_tf32_mma5, cudaFuncAttributeMaxDynamicSharedMemorySize, SMEM_BYTES);
    dim3 grid(16, 128);
    ga_tf32_mma5<<<grid, NTHREADS, SMEM_BYTES>>>(bias, out);
}

// round 8
// speedup vs baseline: 4.2065x; 1.0005x over previous
#include <cuda_runtime.h>
#include <cstdint>

// ---------------------------------------------------------------------------
// GA (3,0,0) fused dense layer as one TF32 mma.sync GEMM.
//   out[k*B+b, d] = sum_j s(k,j) * ( X[i(k,j)*B+b, :] @ W[:, j*D+d] ) + bias[k*D+d]
// M=16384, N=2048, K=16384.
// R8: BSTRIDE 168->136 shrinks the stage so 2 CTAs/SM actually fit
//     (R7's occupancy lever silently failed on the smem ceiling).
// CTA 128x128 / 128 threads, ldmatrix.x4 A frags, 6-stage cp.async ring,
// one barrier per 2 k-tiles, signs via frag XOR, tf32-prerounded scratch.
// ---------------------------------------------------------------------------

#define NTHREADS 128
#define BK 16
#define NKT 1024               // 16384 / BK
#define NPAIRS 512
#define ASZ 2048               // A words per stage: 128*16
#define BSTRIDE 136            // B words per k-row (128 + 8 pad; 136 mod 32 == 8)
#define BSZ (16 * BSTRIDE)     // 2176 words
#define STAGE_W (ASZ + BSZ)    // 4224 words = 16896 B
#define STAGES 6
#define SMEM_BYTES (STAGES * STAGE_W * 4)   // 101376 B per CTA -> 2 CTAs/SM

// 128 MB scratch each: tf32-rounded copies of X and W
__device__ float Xc[16384 * 2048];
__device__ float Wc[2048 * 16384];

// ---------------- Cayley table (validated rounds 1/3/4/5/6/7) ----------------
__device__ __constant__ int c_kij[64] = {
    0,1,2,3,4,5,6,7,  1,0,4,5,2,3,7,6,  2,4,0,6,1,7,3,5,  3,5,6,0,7,1,2,4,
    4,2,1,7,0,6,5,3,  5,3,7,1,6,0,4,2,  6,7,3,2,5,4,0,1,  7,6,5,4,3,2,1,0};
__device__ __constant__ float c_sij[64] = {
    1.f, 1.f, 1.f, 1.f, 1.f, 1.f, 1.f, 1.f,
    1.f, 1.f, 1.f, 1.f, 1.f, 1.f, 1.f, 1.f,
    1.f,-1.f, 1.f, 1.f,-1.f,-1.f, 1.f,-1.f,
    1.f,-1.f,-1.f, 1.f, 1.f,-1.f,-1.f, 1.f,
    1.f,-1.f, 1.f, 1.f,-1.f,-1.f, 1.f,-1.f,
    1.f,-1.f,-1.f, 1.f, 1.f,-1.f,-1.f, 1.f,
    1.f, 1.f,-1.f, 1.f,-1.f, 1.f,-1.f,-1.f,
    1.f, 1.f,-1.f, 1.f,-1.f, 1.f,-1.f,-1.f};

__device__ __forceinline__ void gather_info(int kblk, int j, int& ib, float& sg) {
    int ibv = 0; float sv = 1.f;
#pragma unroll
    for (int ii = 0; ii < 8; ++ii) {
        bool m = (c_kij[ii * 8 + j] == kblk);
        ibv = m ? ii : ibv;
        sv  = m ? c_sij[ii * 8 + j] : sv;
    }
    ib = ibv; sg = sv;
}

__device__ __forceinline__ uint32_t f2tf32(float f) {
    uint32_t r;
    asm("cvt.rna.tf32.f32 %0, %1;" : "=r"(r) : "f"(f));
    return r;
}

__device__ __forceinline__ void mma_tf32(float* d, const uint32_t* a, const uint32_t* b) {
    asm volatile(
        "mma.sync.aligned.m16n8k8.row.col.f32.tf32.tf32.f32 "
        "{%0,%1,%2,%3}, {%4,%5,%6,%7}, {%8,%9}, {%0,%1,%2,%3};"
        : "+f"(d[0]), "+f"(d[1]), "+f"(d[2]), "+f"(d[3])
        : "r"(a[0]), "r"(a[1]), "r"(a[2]), "r"(a[3]), "r"(b[0]), "r"(b[1]));
}

__device__ __forceinline__ void ldsm4(uint32_t* r, uint32_t addr) {
    asm volatile("ldmatrix.sync.aligned.m8n8.x4.shared.b16 {%0,%1,%2,%3}, [%4];"
        : "=r"(r[0]), "=r"(r[1]), "=r"(r[2]), "=r"(r[3]) : "r"(addr));
}

__device__ __forceinline__ uint32_t smem_u32(const void* p) {
    uint32_t a;
    asm("{ .reg .u64 t; cvta.to.shared.u64 t, %1; cvt.u32.u64 %0, t; }" : "=r"(a) : "l"(p));
    return a;
}

__device__ __forceinline__ void cp16(uint32_t dst, const float* src) {
    asm volatile("cp.async.cg.shared.global [%0], [%1], 16;" :: "r"(dst), "l"(src) : "memory");
}
#define CP_COMMIT()  asm volatile("cp.async.commit_group;" ::: "memory")
#define CP_WAIT(n)   asm volatile("cp.async.wait_group %0;" :: "n"(n) : "memory")

// ---------------------------------------------------------------------------
// Preprocess: round X and W to tf32 (RN) so the GEMM's HW truncation is exact.
__global__ __launch_bounds__(256)
void preconv_tf32(const float* __restrict__ X, const float* __restrict__ W)
{
    const size_t i = ((size_t)blockIdx.x * 256 + threadIdx.x) * 4;
    float4 x = *reinterpret_cast<const float4*>(X + i);
    x.x = __uint_as_float(f2tf32(x.x)); x.y = __uint_as_float(f2tf32(x.y));
    x.z = __uint_as_float(f2tf32(x.z)); x.w = __uint_as_float(f2tf32(x.w));
    *reinterpret_cast<float4*>(Xc + i) = x;
    float4 w = *reinterpret_cast<const float4*>(W + i);
    w.x = __uint_as_float(f2tf32(w.x)); w.y = __uint_as_float(f2tf32(w.y));
    w.z = __uint_as_float(f2tf32(w.z)); w.w = __uint_as_float(f2tf32(w.w));
    *reinterpret_cast<float4*>(Wc + i) = w;
}

// ---------------------------------------------------------------------------
__global__ __launch_bounds__(NTHREADS, 2)
void ga_tf32_mma6(const float* __restrict__ bias,  // [16384]
                  float* __restrict__ out)         // [16384, 2048]
{
    extern __shared__ uint32_t sm[];
    const uint32_t sb = smem_u32(sm);

    const int tid  = threadIdx.x;
    const int wid  = tid >> 5;
    const int lane = tid & 31;
    const int q    = lane & 3;
    const int g    = lane >> 2;
    const int wm   = wid >> 1;      // 0..1 (M warps, 64 rows each)
    const int wn   = wid & 1;       // 0..1 (N warps, 64 cols each)

    const int bn   = blockIdx.x;    // 0..15  N tiles (128 wide)
    const int bm   = blockIdx.y;    // 0..127 M tiles (128 tall)
    const int kblk = bm >> 4;       // output blade
    const int rloc = (bm & 15) * 128;

    int      ibA[8];
    uint32_t signbits = 0;
#pragma unroll
    for (int j = 0; j < 8; ++j) {
        int ib; float sg;
        gather_info(kblk, j, ib, sg);
        ibA[j] = ib;
        if (sg < 0.f) signbits |= (1u << j);
    }

    float acc[4][8][4];
#pragma unroll
    for (int f = 0; f < 4; ++f)
#pragma unroll
        for (int n = 0; n < 8; ++n)
#pragma unroll
            for (int e = 0; e < 4; ++e) acc[f][n][e] = 0.f;

    // ---- ldmatrix per-lane address precompute (A fragments) ----
    const int sub    = lane >> 3;
    const int hi     = sub >> 1;
    const int rowoff = (lane & 7) + (sub & 1) * 8;
    uint32_t rbyte[4];
    int      sx[4];
#pragma unroll
    for (int f = 0; f < 4; ++f) {
        const int r = wm * 64 + f * 16 + rowoff;
        rbyte[f] = (uint32_t)(r * 64);
        sx[f]    = (r >> 1) & 3;
    }

    // cp.async thread mappings
    const int a_m = tid >> 2;        // 0..31 (+32*i)
    const int a_c = tid & 3;
    const int b_k = tid >> 5;        // 0..3  (+4*i)
    const int b_n = (tid & 31) * 4;

    auto issue_tile = [&](int kt) {
        const int s  = kt % STAGES;
        const int j  = kt >> 7;
        const int c0 = (kt & 127) * BK;
        const uint32_t As = sb + (uint32_t)(s * STAGE_W * 4);
        const uint32_t Bs = As + ASZ * 4;
        const float* Ap = Xc + ((size_t)(ibA[j] * 2048 + rloc)) * 2048 + c0 + a_c * 4;
#pragma unroll
        for (int i = 0; i < 4; ++i) {
            const int m  = a_m + 32 * i;
            const int ch = a_c ^ ((m >> 1) & 3);
            cp16(As + (uint32_t)((m * 16 + ch * 4) * 4), Ap + (size_t)m * 2048);
        }
        const float* Bp = Wc + (size_t)c0 * 16384 + (size_t)j * 2048 + bn * 128 + b_n;
#pragma unroll
        for (int i = 0; i < 4; ++i)
            cp16(Bs + (uint32_t)(((b_k + 4 * i) * BSTRIDE + b_n) * 4),
                 Bp + (size_t)(b_k + 4 * i) * 16384);
    };

    auto compute_tile = [&](int kt) {
        const int s = kt % STAGES;
        const uint32_t AsAddr = sb + (uint32_t)(s * STAGE_W * 4);
        const uint32_t* Bs = sm + s * STAGE_W + ASZ;
        const uint32_t  smask = ((signbits >> (kt >> 7)) & 1u) << 31;
#pragma unroll
        for (int ks = 0; ks < 2; ++ks) {
            uint32_t afr[4][4], bfr[8][2];
#pragma unroll
            for (int f = 0; f < 4; ++f) {
                const int ch = (2 * ks + hi) ^ sx[f];
                ldsm4(afr[f], AsAddr + rbyte[f] + (uint32_t)(ch * 16));
            }
#pragma unroll
            for (int f = 0; f < 4; ++f) {
                afr[f][0] ^= smask; afr[f][1] ^= smask;
                afr[f][2] ^= smask; afr[f][3] ^= smask;
            }
#pragma unroll
            for (int nf = 0; nf < 8; ++nf) {
                const int n0 = wn * 64 + nf * 8 + g;
                bfr[nf][0] = Bs[(ks * 8 + q    ) * BSTRIDE + n0];
                bfr[nf][1] = Bs[(ks * 8 + q + 4) * BSTRIDE + n0];
            }
#pragma unroll
            for (int f = 0; f < 4; ++f)
#pragma unroll
                for (int nf = 0; nf < 8; ++nf)
                    mma_tf32(acc[f][nf], afr[f], bfr[nf]);
        }
    };

    // prologue: pairs 0 and 1 (tiles 0..3), one commit group per pair
    issue_tile(0); issue_tile(1); CP_COMMIT();
    issue_tile(2); issue_tile(3); CP_COMMIT();

    for (int p = 0; p < NPAIRS; ++p) {
        if (p < NPAIRS - 1) { CP_WAIT(1); } else { CP_WAIT(0); }
        __syncthreads();     // single barrier per pair; protects stage reuse

        if (p + 2 < NPAIRS) {
            issue_tile(2 * p + 4);
            issue_tile(2 * p + 5);
            CP_COMMIT();
        }

        compute_tile(2 * p);
        compute_tile(2 * p + 1);
        // no trailing barrier: next iteration's writes target pair p-1's
        // stages, which every warp finished before this iteration's barrier.
    }

    // ---- epilogue: add blade bias, store ----
    const int ccol = bn * 128 + wn * 64;
    const float* bp = bias + (size_t)kblk * 2048 + ccol;

#pragma unroll
    for (int nf = 0; nf < 8; ++nf) {
        const int cn = nf * 8 + 2 * q;
        const float b0 = bp[cn], b1 = bp[cn + 1];
#pragma unroll
        for (int f = 0; f < 4; ++f) {
            const int r0 = bm * 128 + wm * 64 + f * 16 + g;
            float2 lo  = make_float2(acc[f][nf][0] + b0, acc[f][nf][1] + b1);
            float2 hi2 = make_float2(acc[f][nf][2] + b0, acc[f][nf][3] + b1);
            *reinterpret_cast<float2*>(out + (size_t)r0 * 2048 + ccol + cn)       = lo;
            *reinterpret_cast<float2*>(out + (size_t)(r0 + 8) * 2048 + ccol + cn) = hi2;
        }
    }
}

extern "C" void kernel_launch(void* const* d_in, const int* in_sizes, int n_in,
                              void* d_out, int out_size)
{
    const float* X    = (const float*)d_in[0];
    const float* W    = (const float*)d_in[1];
    const float* bias = (const float*)d_in[2];
    float* out        = (float*)d_out;

    preconv_tf32<<<32768, 256>>>(X, W);

    cudaFuncSetAttribute(ga_tf32_mma6, cudaFuncAttributeMaxDynamicSharedMemorySize, SMEM_BYTES);
    dim3 grid(16, 128);
    ga_tf32_mma6<<<grid, NTHREADS, SMEM_BYTES>>>(bias, out);
}